// round 1
// baseline (speedup 1.0000x reference)
#include <cuda_runtime.h>
#include <cuda_bf16.h>
#include <cstdint>

// Problem constants (from reference)
#define NC 12            // categorical fields
#define NF 4             // continuous fields
#define NTOK 16          // C + F
#define DDIM 128         // embedding dim
#define NPOS (64 * 512)  // B * L = 32768

// Row offsets of each field's sub-table within the fused table (cumsum of VOCABS)
__constant__ int c_offsets[NC] = {
    0, 100000, 100800, 101000, 106000, 106060,
    136060, 136070, 136078, 136128, 138128, 138148
};

__global__ __launch_bounds__(256) void emb_fused_kernel(
    const int*   __restrict__ cat,    // [NPOS, NC]
    const float* __restrict__ cont,   // [NPOS, NF]
    const float* __restrict__ table,  // [V_total, D]
    const float* __restrict__ w,      // [NF, D]
    const float* __restrict__ b,      // [NF, D]
    float4*      __restrict__ out)    // [NPOS, NTOK, D/4]
{
    const unsigned gw   = (blockIdx.x * blockDim.x + threadIdx.x) >> 5; // global warp = output row
    const unsigned lane = threadIdx.x & 31;

    const unsigned c  = gw & (NTOK - 1);  // token channel 0..15 (warp-uniform)
    const unsigned bl = gw >> 4;          // position 0..32767

    float4 v;
    if (c < NC) {
        const int idx = __ldg(&cat[bl * NC + c]);
        if (idx == 0) {
            // padding_idx semantics: row OFFSETS[c] + 0 of the fused table is zeroed
            v = make_float4(0.f, 0.f, 0.f, 0.f);
        } else {
            const long long row = (long long)idx + (long long)c_offsets[c];
            v = __ldg(reinterpret_cast<const float4*>(table + row * DDIM) + lane);
        }
    } else {
        const unsigned f = c - NC;
        const float    x = __ldg(&cont[bl * NF + f]);
        const float4  wv = __ldg(reinterpret_cast<const float4*>(w + f * DDIM) + lane);
        const float4  bv = __ldg(reinterpret_cast<const float4*>(b + f * DDIM) + lane);
        v.x = fmaf(x, wv.x, bv.x);
        v.y = fmaf(x, wv.y, bv.y);
        v.z = fmaf(x, wv.z, bv.z);
        v.w = fmaf(x, wv.w, bv.w);
    }

    // Streaming store: output is write-once, keep the table resident in L2.
    __stcs(out + (size_t)gw * (DDIM / 4) + lane, v);
}

extern "C" void kernel_launch(void* const* d_in, const int* in_sizes, int n_in,
                              void* d_out, int out_size)
{
    const int*   cat   = (const int*)  d_in[0];
    const float* cont  = (const float*)d_in[1];
    const float* table = (const float*)d_in[2];
    const float* w     = (const float*)d_in[3];
    const float* b     = (const float*)d_in[4];
    float4*      out   = (float4*)     d_out;

    // One warp per output row: NPOS * NTOK rows, 32 threads each.
    const unsigned total_threads = NPOS * NTOK * 32;  // 16,777,216
    const unsigned block = 256;
    const unsigned grid  = total_threads / block;     // 65,536

    emb_fused_kernel<<<grid, block>>>(cat, cont, table, w, b, out);
}

// round 2
// speedup vs baseline: 1.1787x; 1.1787x over previous
#include <cuda_runtime.h>
#include <cuda_bf16.h>
#include <cstdint>

// Problem constants (from reference)
#define NC 12            // categorical fields
#define NF 4             // continuous fields
#define NTOK 16          // C + F
#define DDIM 128         // embedding dim
#define NPOS (64 * 512)  // B * L = 32768

// Row offsets of each field's sub-table within the fused table (cumsum of VOCABS)
__constant__ int c_offsets[NC] = {
    0, 100000, 100800, 101000, 106000, 106060,
    136060, 136070, 136078, 136128, 138128, 138148
};

__global__ __launch_bounds__(256) void emb_pos_kernel(
    const int*   __restrict__ cat,    // [NPOS, NC]
    const float* __restrict__ cont,   // [NPOS, NF]
    const float* __restrict__ table,  // [V_total, D]
    const float* __restrict__ w,      // [NF, D]
    const float* __restrict__ b,      // [NF, D]
    float4*      __restrict__ out)    // [NPOS, NTOK, D/4]
{
    const unsigned gw   = (blockIdx.x * blockDim.x + threadIdx.x) >> 5; // warp = position
    const unsigned lane = threadIdx.x & 31;
    const unsigned pos  = gw;                 // 0..NPOS-1 (grid sized exactly)

    // --- coalesced index / scalar loads, once per position ---
    int   my_idx = 0;
    float my_x   = 0.f;
    if (lane < NC) my_idx = __ldg(&cat[pos * NC + lane]);
    if (lane < NF) my_x   = __ldg(&cont[pos * NF + lane]);

    // --- front-batched independent gathers: MLP = 12 ---
    float4 v[NC];
    #pragma unroll
    for (int c = 0; c < NC; c++) {
        const int idx = __shfl_sync(0xffffffffu, my_idx, c);
        // always load (keeps the batch unconditional / predication-free),
        // then select zero for padding_idx
        const int row = idx + c_offsets[c];
        v[c] = __ldg(reinterpret_cast<const float4*>(table) + (size_t)row * (DDIM / 4) + lane);
        if (idx == 0) v[c] = make_float4(0.f, 0.f, 0.f, 0.f);
    }

    // --- 16 contiguous float4 stores: 8 KB contiguous per warp ---
    float4* orow = out + (size_t)pos * (NTOK * DDIM / 4) + lane;
    #pragma unroll
    for (int c = 0; c < NC; c++) {
        __stcs(orow + c * (DDIM / 4), v[c]);
    }

    // --- continuous channels: x * w_f + b_f ---
    #pragma unroll
    for (int f = 0; f < NF; f++) {
        const float  x  = __shfl_sync(0xffffffffu, my_x, f);
        const float4 wv = __ldg(reinterpret_cast<const float4*>(w) + f * (DDIM / 4) + lane);
        const float4 bv = __ldg(reinterpret_cast<const float4*>(b) + f * (DDIM / 4) + lane);
        float4 r;
        r.x = fmaf(x, wv.x, bv.x);
        r.y = fmaf(x, wv.y, bv.y);
        r.z = fmaf(x, wv.z, bv.z);
        r.w = fmaf(x, wv.w, bv.w);
        __stcs(orow + (NC + f) * (DDIM / 4), r);
    }
}

extern "C" void kernel_launch(void* const* d_in, const int* in_sizes, int n_in,
                              void* d_out, int out_size)
{
    const int*   cat   = (const int*)  d_in[0];
    const float* cont  = (const float*)d_in[1];
    const float* table = (const float*)d_in[2];
    const float* w     = (const float*)d_in[3];
    const float* b     = (const float*)d_in[4];
    float4*      out   = (float4*)     d_out;

    // One warp per position: NPOS warps total.
    const unsigned block = 256;                       // 8 warps / block
    const unsigned grid  = NPOS / (block / 32);       // 4096 blocks

    emb_pos_kernel<<<grid, block>>>(cat, cont, table, w, b, out);
}

// round 3
// speedup vs baseline: 1.2298x; 1.0434x over previous
#include <cuda_runtime.h>
#include <cuda_bf16.h>
#include <cstdint>

#define NC 12
#define NF 4
#define NTOK 16
#define DDIM 128
#define NPOS (64 * 512)
#define WARPS_PER_BLOCK 8

// cumsum(VOCABS) offsets, compile-time immediates via unrolled loop
__device__ __forceinline__ constexpr int field_off(int c) {
    constexpr int OFF[NC] = {0, 100000, 100800, 101000, 106000, 106060,
                             136060, 136070, 136078, 136128, 138128, 138148};
    return OFF[c];
}
// small-vocab fields (vocab <= 200): keep rows L1-resident via .ca
__device__ __forceinline__ constexpr bool field_small(int c) {
    constexpr bool S[NC] = {false, false, true, false, true, false,
                            true, true, true, false, true, true};
    return S[c];
}

__device__ __forceinline__ void cp_async16_cg(uint32_t saddr, const void* gptr) {
    asm volatile("cp.async.cg.shared.global [%0], [%1], 16;" :: "r"(saddr), "l"(gptr));
}
__device__ __forceinline__ void cp_async16_ca(uint32_t saddr, const void* gptr) {
    asm volatile("cp.async.ca.shared.global [%0], [%1], 16;" :: "r"(saddr), "l"(gptr));
}

__global__ __launch_bounds__(WARPS_PER_BLOCK * 32) void emb_async_kernel(
    const int*   __restrict__ cat,    // [NPOS, NC]
    const float* __restrict__ cont,   // [NPOS, NF]
    const float* __restrict__ table,  // [V_total, D]
    const float* __restrict__ w,      // [NF, D]
    const float* __restrict__ b,      // [NF, D]
    float4*      __restrict__ out)    // [NPOS, NTOK, D/4]
{
    // staging: [warp][field][lane] float4  = 48 KB
    __shared__ float4 stage[WARPS_PER_BLOCK][NC][32];

    const unsigned warp = threadIdx.x >> 5;
    const unsigned lane = threadIdx.x & 31;
    const unsigned pos  = blockIdx.x * WARPS_PER_BLOCK + warp;

    // coalesced per-position scalars
    int   my_idx = 0;
    float my_x   = 0.f;
    if (lane < NC) my_idx = __ldg(&cat[pos * NC + lane]);
    if (lane < NF) my_x   = __ldg(&cont[pos * NF + lane]);

    // broadcast indices (kept for the padding-zero select at store time)
    int idxs[NC];
    #pragma unroll
    for (int c = 0; c < NC; c++) idxs[c] = __shfl_sync(0xffffffffu, my_idx, c);

    const float4* table4 = reinterpret_cast<const float4*>(table);
    const uint32_t sbase = (uint32_t)__cvta_generic_to_shared(&stage[warp][0][lane]);

    // ---- 12 async row-gathers, all in flight, zero register cost ----
    #pragma unroll
    for (int c = 0; c < NC; c++) {
        const float4* src   = table4 + (size_t)(idxs[c] + field_off(c)) * (DDIM / 4) + lane;
        const uint32_t dstc = sbase + (uint32_t)(c * 32 * sizeof(float4));
        if (field_small(c)) cp_async16_ca(dstc, src);
        else                cp_async16_cg(dstc, src);
    }
    asm volatile("cp.async.commit_group;");

    // ---- overlap: continuous channels (L1-hot w/b) ----
    float4* orow = out + (size_t)pos * (NTOK * DDIM / 4) + lane;
    #pragma unroll
    for (int f = 0; f < NF; f++) {
        const float  x  = __shfl_sync(0xffffffffu, my_x, f);
        const float4 wv = __ldg(reinterpret_cast<const float4*>(w) + f * (DDIM / 4) + lane);
        const float4 bv = __ldg(reinterpret_cast<const float4*>(b) + f * (DDIM / 4) + lane);
        float4 r;
        r.x = fmaf(x, wv.x, bv.x);
        r.y = fmaf(x, wv.y, bv.y);
        r.z = fmaf(x, wv.z, bv.z);
        r.w = fmaf(x, wv.w, bv.w);
        __stcs(orow + (NC + f) * (DDIM / 4), r);
    }

    asm volatile("cp.async.wait_group 0;");
    // each lane reads back exactly the 16B it copied: per-thread visibility, no barrier

    #pragma unroll
    for (int c = 0; c < NC; c++) {
        float4 v = stage[warp][c][lane];
        if (idxs[c] == 0) v = make_float4(0.f, 0.f, 0.f, 0.f);  // padding_idx row is zeroed
        __stcs(orow + c * (DDIM / 4), v);
    }
}

extern "C" void kernel_launch(void* const* d_in, const int* in_sizes, int n_in,
                              void* d_out, int out_size)
{
    const int*   cat   = (const int*)  d_in[0];
    const float* cont  = (const float*)d_in[1];
    const float* table = (const float*)d_in[2];
    const float* w     = (const float*)d_in[3];
    const float* b     = (const float*)d_in[4];
    float4*      out   = (float4*)     d_out;

    const unsigned block = WARPS_PER_BLOCK * 32;       // 256
    const unsigned grid  = NPOS / WARPS_PER_BLOCK;     // 4096

    emb_async_kernel<<<grid, block>>>(cat, cont, table, w, b, out);
}